// round 2
// baseline (speedup 1.0000x reference)
#include <cuda_runtime.h>
#include <math.h>
#include <math_constants.h>

// Problem constants (fixed shapes per reference)
#define NN    50000                // nodes
#define NE    800000               // edges (without self loops)
#define ET    (NE + NN)            // edges + self loops
#define D1    128                  // HEADS*CH  (also F_IN)
#define HEADS 4
#define CH    32
#define CLS   40

// ---------------- scratch (static device allocations) ----------------
static __device__ float g_xl1[NN * D1];
static __device__ float g_xr1[NN * D1];
static __device__ float g_out1[NN * D1];      // accum -> becomes h after elu
static __device__ float g_m1[NN * HEADS];
static __device__ float g_den1[NN * HEADS];
static __device__ float g_e1[(size_t)ET * HEADS];   // logits, then p
static __device__ float g_xl2[NN * CLS];
static __device__ float g_xr2[NN * CLS];
static __device__ float g_out2[NN * CLS];
static __device__ float g_m2[NN];
static __device__ float g_den2[NN];
static __device__ float g_e2[ET];
static __device__ int   g_src[ET];
static __device__ int   g_dst[ET];
static __device__ int   g_is64;

// order-independent float atomic max via int bit tricks
__device__ __forceinline__ void atomicMaxFloat(float* addr, float value) {
    if (value >= 0.f)
        atomicMax((int*)addr, __float_as_int(value));
    else
        atomicMin((unsigned int*)addr, __float_as_uint(value));
}

// ---------------- edge-index dtype detection ----------------
// If buffer is int64 (little endian, values < 2^31), the int32 view is
// [v0,0,v1,0,...]; odd words are all zero. If int32, odd words are random
// node ids — all-zero over 4096 samples is impossible in practice.
__global__ void detect_kernel(const int* __restrict__ w) {
    __shared__ int any_nonzero;
    if (threadIdx.x == 0) any_nonzero = 0;
    __syncthreads();
    int local = 0;
    for (int i = threadIdx.x; i < 4096; i += blockDim.x)
        if (w[2 * i + 1] != 0) local = 1;
    if (local) atomicOr(&any_nonzero, 1);
    __syncthreads();
    if (threadIdx.x == 0) g_is64 = any_nonzero ? 0 : 1;
}

__global__ void convert_kernel(const int* __restrict__ w) {
    int e = blockIdx.x * blockDim.x + threadIdx.x;
    if (e >= ET) return;
    if (e >= NE) { g_src[e] = e - NE; g_dst[e] = e - NE; return; }
    if (g_is64) {
        g_src[e] = w[2 * e];
        g_dst[e] = w[2 * (NE + e)];
    } else {
        g_src[e] = w[e];
        g_dst[e] = w[NE + e];
    }
}

// ---------------- init ----------------
__global__ void init_kernel() {
    int i = blockIdx.x * blockDim.x + threadIdx.x;
    int stride = gridDim.x * blockDim.x;
    for (int j = i; j < NN * D1; j += stride) g_out1[j] = 0.f;
    for (int j = i; j < NN * CLS; j += stride) g_out2[j] = 0.f;
    for (int j = i; j < NN * HEADS; j += stride) { g_m1[j] = -CUDART_INF_F; g_den1[j] = 0.f; }
    for (int j = i; j < NN; j += stride) { g_m2[j] = -CUDART_INF_F; g_den2[j] = 0.f; }
}

// ---------------- layer 1 GEMM: xl1 = x@w1_l, xr1 = x@w1_r ----------------
#define TN1 32
__global__ void gemm1_kernel(const float* __restrict__ x,
                             const float* __restrict__ wl,
                             const float* __restrict__ wr) {
    __shared__ float xs[TN1][D1];
    int n0 = blockIdx.x * TN1;
    int t = threadIdx.x;  // 0..127, output column
    #pragma unroll
    for (int i = 0; i < TN1; i++) {
        int n = n0 + i;
        xs[i][t] = (n < NN) ? x[(size_t)n * D1 + t] : 0.f;
    }
    __syncthreads();
    float accl[TN1], accr[TN1];
    #pragma unroll
    for (int i = 0; i < TN1; i++) { accl[i] = 0.f; accr[i] = 0.f; }
    for (int k = 0; k < D1; k++) {
        float wlv = __ldg(&wl[k * D1 + t]);
        float wrv = __ldg(&wr[k * D1 + t]);
        #pragma unroll
        for (int i = 0; i < TN1; i++) {
            float xv = xs[i][k];
            accl[i] = fmaf(xv, wlv, accl[i]);
            accr[i] = fmaf(xv, wrv, accr[i]);
        }
    }
    for (int i = 0; i < TN1; i++) {
        int n = n0 + i;
        if (n < NN) {
            g_xl1[(size_t)n * D1 + t] = accl[i];
            g_xr1[(size_t)n * D1 + t] = accr[i];
        }
    }
}

// ---------------- layer 1 edge pass A: logits + segment max ----------------
__global__ void edge1_attn(const float* __restrict__ a1) {
    int gw = (blockIdx.x * blockDim.x + threadIdx.x) >> 5;
    int lane = threadIdx.x & 31;
    if (gw >= ET) return;
    int src = g_src[gw];
    int dst = g_dst[gw];
    const float* xl = g_xl1 + (size_t)src * D1;
    const float* xr = g_xr1 + (size_t)dst * D1;
    float ev[HEADS];
    #pragma unroll
    for (int h = 0; h < HEADS; h++) {
        int idx = h * 32 + lane;
        float v = xl[idx] + xr[idx];
        v = (v > 0.f) ? v : 0.2f * v;            // leaky relu
        ev[h] = v * __ldg(&a1[idx]);
    }
    #pragma unroll
    for (int off = 16; off > 0; off >>= 1) {
        #pragma unroll
        for (int h = 0; h < HEADS; h++)
            ev[h] += __shfl_xor_sync(0xffffffffu, ev[h], off);
    }
    if (lane == 0) {
        #pragma unroll
        for (int h = 0; h < HEADS; h++) {
            g_e1[(size_t)gw * HEADS + h] = ev[h];
            atomicMaxFloat(&g_m1[dst * HEADS + h], ev[h]);
        }
    }
}

// ---------------- layer 1 edge pass B: exp + denom ----------------
__global__ void edge1_exp() {
    int id = blockIdx.x * blockDim.x + threadIdx.x;
    if (id >= ET * HEADS) return;
    int e = id >> 2;
    int h = id & 3;
    int dst = g_dst[e];
    float p = __expf(g_e1[id] - g_m1[dst * HEADS + h]);
    g_e1[id] = p;
    atomicAdd(&g_den1[dst * HEADS + h], p);
}

// ---------------- layer 1 edge pass C: weighted scatter ----------------
__global__ void edge1_aggr() {
    int gw = (blockIdx.x * blockDim.x + threadIdx.x) >> 5;
    int lane = threadIdx.x & 31;
    if (gw >= ET) return;
    int src = g_src[gw];
    int dst = g_dst[gw];
    float alpha[HEADS];
    #pragma unroll
    for (int h = 0; h < HEADS; h++)
        alpha[h] = g_e1[(size_t)gw * HEADS + h] / g_den1[dst * HEADS + h];
    const float* xl = g_xl1 + (size_t)src * D1;
    float* out = g_out1 + (size_t)dst * D1;
    #pragma unroll
    for (int h = 0; h < HEADS; h++) {
        int idx = h * 32 + lane;
        atomicAdd(&out[idx], alpha[h] * xl[idx]);
    }
}

// ---------------- elu(out1 + b1) in place ----------------
__global__ void elu_kernel(const float* __restrict__ b1) {
    int i = blockIdx.x * blockDim.x + threadIdx.x;
    if (i >= NN * D1) return;
    float v = g_out1[i] + b1[i & (D1 - 1)];
    g_out1[i] = (v > 0.f) ? v : (__expf(v) - 1.f);
}

// ---------------- layer 2 GEMM: xl2 = h@w2_l, xr2 = h@w2_r ----------------
#define TN2 16
__global__ void gemm2_kernel(const float* __restrict__ wl,
                             const float* __restrict__ wr) {
    __shared__ float hs[TN2][D1];
    int n0 = blockIdx.x * TN2;
    int t = threadIdx.x;  // 0..127
    #pragma unroll
    for (int i = 0; i < TN2; i++) {
        int n = n0 + i;
        hs[i][t] = (n < NN) ? g_out1[(size_t)n * D1 + t] : 0.f;
    }
    __syncthreads();
    if (t >= 2 * CLS) return;
    const float* w = (t < CLS) ? wl : wr;
    int col = (t < CLS) ? t : t - CLS;
    float acc[TN2];
    #pragma unroll
    for (int i = 0; i < TN2; i++) acc[i] = 0.f;
    for (int k = 0; k < D1; k++) {
        float wv = __ldg(&w[k * CLS + col]);
        #pragma unroll
        for (int i = 0; i < TN2; i++)
            acc[i] = fmaf(hs[i][k], wv, acc[i]);
    }
    for (int i = 0; i < TN2; i++) {
        int n = n0 + i;
        if (n < NN) {
            if (t < CLS) g_xl2[(size_t)n * CLS + col] = acc[i];
            else         g_xr2[(size_t)n * CLS + col] = acc[i];
        }
    }
}

// ---------------- layer 2 edge pass A ----------------
__global__ void edge2_attn(const float* __restrict__ a2) {
    int gw = (blockIdx.x * blockDim.x + threadIdx.x) >> 5;
    int lane = threadIdx.x & 31;
    if (gw >= ET) return;
    int src = g_src[gw];
    int dst = g_dst[gw];
    const float* xl = g_xl2 + (size_t)src * CLS;
    const float* xr = g_xr2 + (size_t)dst * CLS;
    float v0 = xl[lane] + xr[lane];
    v0 = (v0 > 0.f) ? v0 : 0.2f * v0;
    float s = v0 * __ldg(&a2[lane]);
    if (lane < CLS - 32) {
        int c = lane + 32;
        float v1 = xl[c] + xr[c];
        v1 = (v1 > 0.f) ? v1 : 0.2f * v1;
        s += v1 * __ldg(&a2[c]);
    }
    #pragma unroll
    for (int off = 16; off > 0; off >>= 1)
        s += __shfl_xor_sync(0xffffffffu, s, off);
    if (lane == 0) {
        g_e2[gw] = s;
        atomicMaxFloat(&g_m2[dst], s);
    }
}

// ---------------- layer 2 edge pass B ----------------
__global__ void edge2_exp() {
    int e = blockIdx.x * blockDim.x + threadIdx.x;
    if (e >= ET) return;
    int dst = g_dst[e];
    float p = __expf(g_e2[e] - g_m2[dst]);
    g_e2[e] = p;
    atomicAdd(&g_den2[dst], p);
}

// ---------------- layer 2 edge pass C ----------------
__global__ void edge2_aggr() {
    int gw = (blockIdx.x * blockDim.x + threadIdx.x) >> 5;
    int lane = threadIdx.x & 31;
    if (gw >= ET) return;
    int src = g_src[gw];
    int dst = g_dst[gw];
    float alpha = g_e2[gw] / g_den2[dst];
    const float* xl = g_xl2 + (size_t)src * CLS;
    float* out = g_out2 + (size_t)dst * CLS;
    atomicAdd(&out[lane], alpha * xl[lane]);
    if (lane < CLS - 32)
        atomicAdd(&out[lane + 32], alpha * xl[lane + 32]);
}

// ---------------- final: +b2 then log_softmax ----------------
__global__ void final_kernel(const float* __restrict__ b2,
                             float* __restrict__ out) {
    int n = (blockIdx.x * blockDim.x + threadIdx.x) >> 5;
    int lane = threadIdx.x & 31;
    if (n >= NN) return;
    const float* o = g_out2 + (size_t)n * CLS;
    float v0 = o[lane] + __ldg(&b2[lane]);
    float v1 = (lane < CLS - 32) ? (o[lane + 32] + __ldg(&b2[lane + 32])) : -CUDART_INF_F;
    float m = fmaxf(v0, v1);
    #pragma unroll
    for (int off = 16; off > 0; off >>= 1)
        m = fmaxf(m, __shfl_xor_sync(0xffffffffu, m, off));
    float s = __expf(v0 - m) + ((lane < CLS - 32) ? __expf(v1 - m) : 0.f);
    #pragma unroll
    for (int off = 16; off > 0; off >>= 1)
        s += __shfl_xor_sync(0xffffffffu, s, off);
    float lse = m + logf(s);
    out[(size_t)n * CLS + lane] = v0 - lse;
    if (lane < CLS - 32)
        out[(size_t)n * CLS + lane + 32] = v1 - lse;
}

// ---------------- launch ----------------
extern "C" void kernel_launch(void* const* d_in, const int* in_sizes, int n_in,
                              void* d_out, int out_size) {
    const float* x    = (const float*)d_in[0];
    const int*   eiw  = (const int*)d_in[1];   // int32 view of edge_index (int32 or int64)
    const float* w1_l = (const float*)d_in[2];
    const float* w1_r = (const float*)d_in[3];
    const float* a1   = (const float*)d_in[4];
    const float* b1   = (const float*)d_in[5];
    const float* w2_l = (const float*)d_in[6];
    const float* w2_r = (const float*)d_in[7];
    const float* a2   = (const float*)d_in[8];
    const float* b2   = (const float*)d_in[9];
    float*       out  = (float*)d_out;

    detect_kernel<<<1, 256>>>(eiw);
    convert_kernel<<<(ET + 255) / 256, 256>>>(eiw);
    init_kernel<<<1024, 256>>>();
    gemm1_kernel<<<(NN + TN1 - 1) / TN1, D1>>>(x, w1_l, w1_r);

    int edge_warp_blocks = (ET * 32 + 255) / 256;
    edge1_attn<<<edge_warp_blocks, 256>>>(a1);
    edge1_exp<<<(ET * HEADS + 255) / 256, 256>>>();
    edge1_aggr<<<edge_warp_blocks, 256>>>();

    elu_kernel<<<(NN * D1 + 255) / 256, 256>>>(b1);
    gemm2_kernel<<<(NN + TN2 - 1) / TN2, D1>>>(w2_l, w2_r);

    edge2_attn<<<edge_warp_blocks, 256>>>(a2);
    edge2_exp<<<(ET + 255) / 256, 256>>>();
    edge2_aggr<<<edge_warp_blocks, 256>>>();

    final_kernel<<<(NN * 32 + 255) / 256, 256>>>(b2, out);
}

// round 3
// speedup vs baseline: 2.6934x; 2.6934x over previous
#include <cuda_runtime.h>
#include <math.h>
#include <math_constants.h>

// Problem constants (fixed shapes per reference)
#define NN    50000                // nodes
#define NE    800000               // edges (without self loops)
#define ET    (NE + NN)            // edges + self loops
#define D1    128                  // HEADS*CH  (also F_IN)
#define HEADS 4
#define CH    32
#define CLS   40
#define SCANB 1024
#define NBLK  ((NN + SCANB - 1) / SCANB)   // 49

// ---------------- scratch (static device allocations) ----------------
static __device__ float g_xl1[(size_t)NN * D1];
static __device__ float g_xr1[(size_t)NN * D1];
static __device__ float g_h  [(size_t)NN * D1];
static __device__ float g_xl2[(size_t)NN * CLS];
static __device__ float g_xr2[(size_t)NN * CLS];
static __device__ int   g_src[ET];
static __device__ int   g_dst[ET];
static __device__ int   g_deg[NN];
static __device__ int   g_incl[NBLK * SCANB];
static __device__ int   g_bsum[NBLK];
static __device__ int   g_boff[NBLK];
static __device__ int   g_rowptr[NN + 1];
static __device__ int   g_cursor[NN];
static __device__ int   g_csrc[ET];
static __device__ int   g_is64;

// ---------------- f32x2 helpers (Blackwell packed fp32) ----------------
__device__ __forceinline__ unsigned long long pk2(float a, float b) {
    unsigned long long r;
    asm("mov.b64 %0, {%1,%2};" : "=l"(r) : "f"(a), "f"(b));
    return r;
}
__device__ __forceinline__ unsigned long long fma2(unsigned long long a,
                                                   unsigned long long b,
                                                   unsigned long long c) {
    unsigned long long d;
    asm("fma.rn.f32x2 %0, %1, %2, %3;" : "=l"(d) : "l"(a), "l"(b), "l"(c));
    return d;
}
__device__ __forceinline__ float2 upk2(unsigned long long v) {
    float2 f;
    asm("mov.b64 {%0,%1}, %2;" : "=f"(f.x), "=f"(f.y) : "l"(v));
    return f;
}

__device__ __forceinline__ float lrelu(float v) {
    return (v > 0.f) ? v : 0.2f * v;
}

// ---------------- edge-index dtype detection ----------------
// int64 little-endian with values < 2^31: odd int32 words are all zero.
__global__ void detect_kernel(const int* __restrict__ w) {
    __shared__ int any_nonzero;
    if (threadIdx.x == 0) any_nonzero = 0;
    __syncthreads();
    int local = 0;
    for (int i = threadIdx.x; i < 4096; i += blockDim.x)
        if (w[2 * i + 1] != 0) local = 1;
    if (local) atomicOr(&any_nonzero, 1);
    __syncthreads();
    if (threadIdx.x == 0) g_is64 = any_nonzero ? 0 : 1;
}

__global__ void zero_deg_kernel() {
    int i = blockIdx.x * blockDim.x + threadIdx.x;
    if (i < NN) g_deg[i] = 0;
}

// convert edge index to int32 src/dst (self loops appended) + dst histogram
__global__ void conv_hist_kernel(const int* __restrict__ w) {
    int e = blockIdx.x * blockDim.x + threadIdx.x;
    if (e >= ET) return;
    int src, dst;
    if (e >= NE) {
        src = e - NE; dst = src;
    } else if (g_is64) {
        src = w[2 * e];
        dst = w[2 * (NE + e)];
    } else {
        src = w[e];
        dst = w[NE + e];
    }
    g_src[e] = src;
    g_dst[e] = dst;
    atomicAdd(&g_deg[dst], 1);
}

// ---------------- 3-kernel exclusive scan of deg -> rowptr, cursor ------
__global__ void scan1_kernel() {
    __shared__ int sm[SCANB];
    int t = threadIdx.x;
    int i = blockIdx.x * SCANB + t;
    sm[t] = (i < NN) ? g_deg[i] : 0;
    __syncthreads();
    for (int off = 1; off < SCANB; off <<= 1) {
        int add = (t >= off) ? sm[t - off] : 0;
        __syncthreads();
        sm[t] += add;
        __syncthreads();
    }
    g_incl[i] = sm[t];
    if (t == SCANB - 1) g_bsum[blockIdx.x] = sm[t];
}

__global__ void scan2_kernel() {
    if (threadIdx.x == 0) {
        int s = 0;
        for (int b = 0; b < NBLK; b++) { g_boff[b] = s; s += g_bsum[b]; }
    }
}

__global__ void scan3_kernel() {
    int i = blockIdx.x * blockDim.x + threadIdx.x;
    if (i >= NN) return;
    int incl = g_incl[i] + g_boff[i >> 10];
    g_rowptr[i + 1] = incl;
    g_cursor[i] = incl - g_deg[i];
    if (i == 0) g_rowptr[0] = 0;
}

__global__ void scatter_kernel() {
    int e = blockIdx.x * blockDim.x + threadIdx.x;
    if (e >= ET) return;
    int dst = g_dst[e];
    int pos = atomicAdd(&g_cursor[dst], 1);
    g_csrc[pos] = g_src[e];
}

// ---------------- layer 1 GEMM: xl1 = x@w1_l, xr1 = x@w1_r (f32x2) -------
#define TN1 32
__global__ __launch_bounds__(128) void gemm1_kernel(const float* __restrict__ x,
                                                    const float* __restrict__ wl,
                                                    const float* __restrict__ wr) {
    __shared__ float xs[TN1][D1];
    int n0 = blockIdx.x * TN1;
    int t = threadIdx.x;  // output column 0..127
    #pragma unroll
    for (int i = 0; i < TN1; i++) {
        int n = n0 + i;
        xs[i][t] = (n < NN) ? x[(size_t)n * D1 + t] : 0.f;
    }
    __syncthreads();
    unsigned long long acc[TN1];
    #pragma unroll
    for (int i = 0; i < TN1; i++) acc[i] = 0ull;
    for (int k = 0; k < D1; k += 4) {
        unsigned long long w2[4];
        #pragma unroll
        for (int kk = 0; kk < 4; kk++)
            w2[kk] = pk2(__ldg(&wl[(k + kk) * D1 + t]), __ldg(&wr[(k + kk) * D1 + t]));
        #pragma unroll
        for (int i = 0; i < TN1; i++) {
            const float4 xv = *reinterpret_cast<const float4*>(&xs[i][k]);
            acc[i] = fma2(pk2(xv.x, xv.x), w2[0], acc[i]);
            acc[i] = fma2(pk2(xv.y, xv.y), w2[1], acc[i]);
            acc[i] = fma2(pk2(xv.z, xv.z), w2[2], acc[i]);
            acc[i] = fma2(pk2(xv.w, xv.w), w2[3], acc[i]);
        }
    }
    #pragma unroll
    for (int i = 0; i < TN1; i++) {
        int n = n0 + i;
        if (n < NN) {
            float2 lr = upk2(acc[i]);
            g_xl1[(size_t)n * D1 + t] = lr.x;
            g_xr1[(size_t)n * D1 + t] = lr.y;
        }
    }
}

// ---------------- fused node kernel, layer 1 -----------------------------
// One warp per dst node. Lane owns features f0..f0+3 (f0 = lane*4), all in
// head h = lane/8. Online softmax per head; 8-lane butterfly reduction.
__global__ void node1_kernel(const float* __restrict__ a1,
                             const float* __restrict__ b1) {
    int n = (blockIdx.x * blockDim.x + threadIdx.x) >> 5;
    int lane = threadIdx.x & 31;
    if (n >= NN) return;
    int f0 = lane * 4;
    const float4 xr4 = *reinterpret_cast<const float4*>(&g_xr1[(size_t)n * D1 + f0]);
    const float4 a4  = __ldg(reinterpret_cast<const float4*>(&a1[f0]));
    int beg = g_rowptr[n];
    int end = g_rowptr[n + 1];

    float m = -CUDART_INF_F, den = 0.f;
    float ax = 0.f, ay = 0.f, az = 0.f, aw = 0.f;

    int j = beg;
    int src = g_csrc[j];
    float4 xl = *reinterpret_cast<const float4*>(&g_xl1[(size_t)src * D1 + f0]);
    while (j < end) {
        ++j;
        int nsrc = (j < end) ? g_csrc[j] : 0;
        const float4 nxl = *reinterpret_cast<const float4*>(&g_xl1[(size_t)nsrc * D1 + f0]);

        float s = lrelu(xl.x + xr4.x) * a4.x
                + lrelu(xl.y + xr4.y) * a4.y
                + lrelu(xl.z + xr4.z) * a4.z
                + lrelu(xl.w + xr4.w) * a4.w;
        s += __shfl_xor_sync(0xffffffffu, s, 1);
        s += __shfl_xor_sync(0xffffffffu, s, 2);
        s += __shfl_xor_sync(0xffffffffu, s, 4);   // head logit, uniform in 8-lane group

        float nm = fmaxf(m, s);
        float scale = __expf(m - nm);
        float p = __expf(s - nm);
        den = den * scale + p;
        ax = ax * scale + p * xl.x;
        ay = ay * scale + p * xl.y;
        az = az * scale + p * xl.z;
        aw = aw * scale + p * xl.w;
        m = nm;
        xl = nxl;
    }
    float inv = 1.f / den;
    const float4 b4 = __ldg(reinterpret_cast<const float4*>(&b1[f0]));
    float4 o;
    o.x = ax * inv + b4.x; o.x = (o.x > 0.f) ? o.x : (__expf(o.x) - 1.f);
    o.y = ay * inv + b4.y; o.y = (o.y > 0.f) ? o.y : (__expf(o.y) - 1.f);
    o.z = az * inv + b4.z; o.z = (o.z > 0.f) ? o.z : (__expf(o.z) - 1.f);
    o.w = aw * inv + b4.w; o.w = (o.w > 0.f) ? o.w : (__expf(o.w) - 1.f);
    *reinterpret_cast<float4*>(&g_h[(size_t)n * D1 + f0]) = o;
}

// ---------------- layer 2 GEMM: xl2 = h@w2_l, xr2 = h@w2_r (f32x2) -------
#define TN2 32
#define G2T 160
__global__ __launch_bounds__(G2T) void gemm2_kernel(const float* __restrict__ wl,
                                                    const float* __restrict__ wr) {
    __shared__ float hs[TN2][D1];
    int n0 = blockIdx.x * TN2;
    int t = threadIdx.x;  // 0..159
    for (int idx = t; idx < TN2 * D1; idx += G2T) {
        int row = idx >> 7, col = idx & 127;
        int n = n0 + row;
        hs[row][col] = (n < NN) ? g_h[(size_t)n * D1 + col] : 0.f;
    }
    __syncthreads();
    int col = t % CLS;     // 0..39
    int q   = t / CLS;     // 0..3 -> rows q*8..q*8+7
    unsigned long long acc[8];
    #pragma unroll
    for (int r = 0; r < 8; r++) acc[r] = 0ull;
    for (int k = 0; k < D1; k++) {
        unsigned long long w2 = pk2(__ldg(&wl[k * CLS + col]), __ldg(&wr[k * CLS + col]));
        #pragma unroll
        for (int r = 0; r < 8; r++) {
            float hv = hs[q * 8 + r][k];
            acc[r] = fma2(pk2(hv, hv), w2, acc[r]);
        }
    }
    #pragma unroll
    for (int r = 0; r < 8; r++) {
        int n = n0 + q * 8 + r;
        if (n < NN) {
            float2 lr = upk2(acc[r]);
            g_xl2[(size_t)n * CLS + col] = lr.x;
            g_xr2[(size_t)n * CLS + col] = lr.y;
        }
    }
}

// ---------------- fused node kernel, layer 2 + log_softmax ---------------
// One warp per node; lanes 0..19 own features {lane*2, lane*2+1}. Single head.
__global__ void node2_kernel(const float* __restrict__ a2,
                             const float* __restrict__ b2,
                             float* __restrict__ out) {
    int n = (blockIdx.x * blockDim.x + threadIdx.x) >> 5;
    int lane = threadIdx.x & 31;
    if (n >= NN) return;
    bool act = (lane * 2) < CLS;
    int f0 = lane * 2;
    float2 xr2v = make_float2(0.f, 0.f), a2v = make_float2(0.f, 0.f);
    if (act) {
        xr2v = *reinterpret_cast<const float2*>(&g_xr2[(size_t)n * CLS + f0]);
        a2v  = __ldg(reinterpret_cast<const float2*>(&a2[f0]));
    }
    int beg = g_rowptr[n];
    int end = g_rowptr[n + 1];

    float m = -CUDART_INF_F, den = 0.f, ax = 0.f, ay = 0.f;

    int j = beg;
    int src = g_csrc[j];
    float2 xl = act ? *reinterpret_cast<const float2*>(&g_xl2[(size_t)src * CLS + f0])
                    : make_float2(0.f, 0.f);
    while (j < end) {
        ++j;
        int nsrc = (j < end) ? g_csrc[j] : 0;
        const float2 nxl = act ? *reinterpret_cast<const float2*>(&g_xl2[(size_t)nsrc * CLS + f0])
                               : make_float2(0.f, 0.f);

        float s = lrelu(xl.x + xr2v.x) * a2v.x + lrelu(xl.y + xr2v.y) * a2v.y;
        #pragma unroll
        for (int off = 16; off > 0; off >>= 1)
            s += __shfl_xor_sync(0xffffffffu, s, off);

        float nm = fmaxf(m, s);
        float scale = __expf(m - nm);
        float p = __expf(s - nm);
        den = den * scale + p;
        ax = ax * scale + p * xl.x;
        ay = ay * scale + p * xl.y;
        m = nm;
        xl = nxl;
    }
    float inv = 1.f / den;
    float v0 = -CUDART_INF_F, v1 = -CUDART_INF_F;
    if (act) {
        v0 = ax * inv + __ldg(&b2[f0]);
        v1 = ay * inv + __ldg(&b2[f0 + 1]);
    }
    float mx = fmaxf(v0, v1);
    #pragma unroll
    for (int off = 16; off > 0; off >>= 1)
        mx = fmaxf(mx, __shfl_xor_sync(0xffffffffu, mx, off));
    float se = act ? (__expf(v0 - mx) + __expf(v1 - mx)) : 0.f;
    #pragma unroll
    for (int off = 16; off > 0; off >>= 1)
        se += __shfl_xor_sync(0xffffffffu, se, off);
    float lse = mx + logf(se);
    if (act) {
        float2 o = make_float2(v0 - lse, v1 - lse);
        *reinterpret_cast<float2*>(&out[(size_t)n * CLS + f0]) = o;
    }
}

// ---------------- launch ----------------
extern "C" void kernel_launch(void* const* d_in, const int* in_sizes, int n_in,
                              void* d_out, int out_size) {
    const float* x    = (const float*)d_in[0];
    const int*   eiw  = (const int*)d_in[1];   // int32 view (int32 or int64 data)
    const float* w1_l = (const float*)d_in[2];
    const float* w1_r = (const float*)d_in[3];
    const float* a1   = (const float*)d_in[4];
    const float* b1   = (const float*)d_in[5];
    const float* w2_l = (const float*)d_in[6];
    const float* w2_r = (const float*)d_in[7];
    const float* a2   = (const float*)d_in[8];
    const float* b2   = (const float*)d_in[9];
    float*       out  = (float*)d_out;

    // CSR build
    detect_kernel<<<1, 256>>>(eiw);
    zero_deg_kernel<<<(NN + 255) / 256, 256>>>();
    conv_hist_kernel<<<(ET + 255) / 256, 256>>>(eiw);
    scan1_kernel<<<NBLK, SCANB>>>();
    scan2_kernel<<<1, 32>>>();
    scan3_kernel<<<(NN + 255) / 256, 256>>>();
    scatter_kernel<<<(ET + 255) / 256, 256>>>();

    // layer 1
    gemm1_kernel<<<(NN + TN1 - 1) / TN1, 128>>>(x, w1_l, w1_r);
    node1_kernel<<<(NN * 32 + 255) / 256, 256>>>(a1, b1);

    // layer 2
    gemm2_kernel<<<(NN + TN2 - 1) / TN2, G2T>>>(w2_l, w2_r);
    node2_kernel<<<(NN * 32 + 255) / 256, 256>>>(a2, b2, out);
}

// round 4
// speedup vs baseline: 2.8377x; 1.0536x over previous
#include <cuda_runtime.h>
#include <math.h>
#include <math_constants.h>

// Problem constants (fixed shapes per reference)
#define NN    50000                // nodes
#define NE    800000               // edges (without self loops)
#define ET    (NE + NN)            // edges + self loops
#define D1    128                  // HEADS*CH  (also F_IN)
#define HEADS 4
#define CH    32
#define CLS   40
#define SCANB 1024
#define NBLK  ((NN + SCANB - 1) / SCANB)   // 49

typedef unsigned long long ull;

// ---------------- scratch (static device allocations) ----------------
static __device__ float g_xl1[(size_t)NN * D1];
static __device__ float g_xr1[(size_t)NN * D1];
static __device__ float g_h  [(size_t)NN * D1];
static __device__ float g_xl2[(size_t)NN * CLS];
static __device__ float g_xr2[(size_t)NN * CLS];
static __device__ int   g_src[ET];
static __device__ int   g_dst[ET];
static __device__ int   g_deg[NN];
static __device__ int   g_incl[NBLK * SCANB];
static __device__ int   g_bsum[NBLK];
static __device__ int   g_boff[NBLK];
static __device__ int   g_rowptr[NN + 1];
static __device__ int   g_cursor[NN];
static __device__ int   g_csrc[ET];
static __device__ int   g_is64;

// ---------------- stream/event objects (created at process start) -------
static cudaStream_t s_side;
static cudaEvent_t  s_ev_fork;
static cudaEvent_t  s_ev_join;
namespace {
struct StreamInit {
    StreamInit() {
        cudaStreamCreateWithFlags(&s_side, cudaStreamNonBlocking);
        cudaEventCreateWithFlags(&s_ev_fork, cudaEventDisableTiming);
        cudaEventCreateWithFlags(&s_ev_join, cudaEventDisableTiming);
    }
};
static StreamInit s_stream_init;
}

// ---------------- f32x2 helpers (Blackwell packed fp32) ----------------
__device__ __forceinline__ ull pk2(float a, float b) {
    ull r;
    asm("mov.b64 %0, {%1,%2};" : "=l"(r) : "f"(a), "f"(b));
    return r;
}
__device__ __forceinline__ ull fma2(ull a, ull b, ull c) {
    ull d;
    asm("fma.rn.f32x2 %0, %1, %2, %3;" : "=l"(d) : "l"(a), "l"(b), "l"(c));
    return d;
}
__device__ __forceinline__ float2 upk2(ull v) {
    float2 f;
    asm("mov.b64 {%0,%1}, %2;" : "=f"(f.x), "=f"(f.y) : "l"(v));
    return f;
}

__device__ __forceinline__ float lrelu(float v) {
    return (v > 0.f) ? v : 0.2f * v;
}

// ---------------- CSR build -------------------------------------------
// detect int64 vs int32 edge_index + zero degree histogram (fused).
__global__ void detect_zero_kernel(const int* __restrict__ w) {
    int i = blockIdx.x * blockDim.x + threadIdx.x;
    if (i < NN) g_deg[i] = 0;
    if (blockIdx.x == 0) {
        __shared__ int any_nonzero;
        if (threadIdx.x == 0) any_nonzero = 0;
        __syncthreads();
        int local = 0;
        for (int k = threadIdx.x; k < 4096; k += blockDim.x)
            if (w[2 * k + 1] != 0) local = 1;
        if (local) atomicOr(&any_nonzero, 1);
        __syncthreads();
        if (threadIdx.x == 0) g_is64 = any_nonzero ? 0 : 1;
    }
}

// convert edge index to int32 src/dst (self loops appended) + dst histogram
__global__ void conv_hist_kernel(const int* __restrict__ w) {
    int e = blockIdx.x * blockDim.x + threadIdx.x;
    if (e >= ET) return;
    int src, dst;
    if (e >= NE) {
        src = e - NE; dst = src;
    } else if (g_is64) {
        src = w[2 * e];
        dst = w[2 * (NE + e)];
    } else {
        src = w[e];
        dst = w[NE + e];
    }
    g_src[e] = src;
    g_dst[e] = dst;
    atomicAdd(&g_deg[dst], 1);
}

__global__ void scan1_kernel() {
    __shared__ int sm[SCANB];
    int t = threadIdx.x;
    int i = blockIdx.x * SCANB + t;
    sm[t] = (i < NN) ? g_deg[i] : 0;
    __syncthreads();
    for (int off = 1; off < SCANB; off <<= 1) {
        int add = (t >= off) ? sm[t - off] : 0;
        __syncthreads();
        sm[t] += add;
        __syncthreads();
    }
    g_incl[i] = sm[t];
    if (t == SCANB - 1) g_bsum[blockIdx.x] = sm[t];
}

__global__ void scan2_kernel() {
    __shared__ int sm[64];
    int t = threadIdx.x;  // 64 threads
    int v = (t < NBLK) ? g_bsum[t] : 0;
    sm[t] = v;
    __syncthreads();
    #pragma unroll
    for (int off = 1; off < 64; off <<= 1) {
        int add = (t >= off) ? sm[t - off] : 0;
        __syncthreads();
        sm[t] += add;
        __syncthreads();
    }
    if (t < NBLK) g_boff[t] = sm[t] - v;   // exclusive
}

__global__ void scan3_kernel() {
    int i = blockIdx.x * blockDim.x + threadIdx.x;
    if (i >= NN) return;
    int incl = g_incl[i] + g_boff[i >> 10];
    g_rowptr[i + 1] = incl;
    g_cursor[i] = incl - g_deg[i];
    if (i == 0) g_rowptr[0] = 0;
}

__global__ void scatter_kernel() {
    int e = blockIdx.x * blockDim.x + threadIdx.x;
    if (e >= ET) return;
    int dst = g_dst[e];
    int pos = atomicAdd(&g_cursor[dst], 1);
    g_csrc[pos] = g_src[e];
}

// ---------------- layer 1 GEMM: xl1 = x@w1_l, xr1 = x@w1_r (f32x2) -------
// 128 threads; thread owns 2 adjacent columns x 16 rows; each x broadcast
// pack feeds 2 FMA2 -> FMA-pipe bound.
#define TN1 32
__global__ __launch_bounds__(128) void gemm1_kernel(const float* __restrict__ x,
                                                    const float* __restrict__ wl,
                                                    const float* __restrict__ wr) {
    __shared__ float xs[TN1][D1];
    int n0 = blockIdx.x * TN1;
    int t = threadIdx.x;  // 0..127
    #pragma unroll
    for (int i = 0; i < TN1; i++) {
        int n = n0 + i;
        xs[i][t] = (n < NN) ? x[(size_t)n * D1 + t] : 0.f;
    }
    __syncthreads();
    const int r0 = (t >> 6) * 16;   // rows r0..r0+15
    const int c  = (t & 63) * 2;    // columns c, c+1
    ull accA[16], accB[16];
    #pragma unroll
    for (int i = 0; i < 16; i++) { accA[i] = 0ull; accB[i] = 0ull; }
    for (int k = 0; k < D1; k += 4) {
        ull wa[4], wb[4];
        #pragma unroll
        for (int kk = 0; kk < 4; kk++) {
            wa[kk] = pk2(__ldg(&wl[(k + kk) * D1 + c]),     __ldg(&wr[(k + kk) * D1 + c]));
            wb[kk] = pk2(__ldg(&wl[(k + kk) * D1 + c + 1]), __ldg(&wr[(k + kk) * D1 + c + 1]));
        }
        #pragma unroll
        for (int i = 0; i < 16; i++) {
            const float4 xv = *reinterpret_cast<const float4*>(&xs[r0 + i][k]);
            ull xp;
            xp = pk2(xv.x, xv.x); accA[i] = fma2(xp, wa[0], accA[i]); accB[i] = fma2(xp, wb[0], accB[i]);
            xp = pk2(xv.y, xv.y); accA[i] = fma2(xp, wa[1], accA[i]); accB[i] = fma2(xp, wb[1], accB[i]);
            xp = pk2(xv.z, xv.z); accA[i] = fma2(xp, wa[2], accA[i]); accB[i] = fma2(xp, wb[2], accB[i]);
            xp = pk2(xv.w, xv.w); accA[i] = fma2(xp, wa[3], accA[i]); accB[i] = fma2(xp, wb[3], accB[i]);
        }
    }
    #pragma unroll
    for (int i = 0; i < 16; i++) {
        int n = n0 + r0 + i;
        if (n < NN) {
            float2 A = upk2(accA[i]);   // (l[c], r[c])
            float2 B = upk2(accB[i]);   // (l[c+1], r[c+1])
            *reinterpret_cast<float2*>(&g_xl1[(size_t)n * D1 + c]) = make_float2(A.x, B.x);
            *reinterpret_cast<float2*>(&g_xr1[(size_t)n * D1 + c]) = make_float2(A.y, B.y);
        }
    }
}

// ---------------- fused node kernel, layer 1 -----------------------------
// One warp per dst node, depth-2 gather pipeline, online softmax per head.
__global__ void node1_kernel(const float* __restrict__ a1,
                             const float* __restrict__ b1) {
    int n = (blockIdx.x * blockDim.x + threadIdx.x) >> 5;
    int lane = threadIdx.x & 31;
    if (n >= NN) return;
    int f0 = lane * 4;
    const float4 xr4 = *reinterpret_cast<const float4*>(&g_xr1[(size_t)n * D1 + f0]);
    const float4 a4  = __ldg(reinterpret_cast<const float4*>(&a1[f0]));
    int beg = g_rowptr[n];
    int end = g_rowptr[n + 1];

    float m = -CUDART_INF_F, den = 0.f;
    float ax = 0.f, ay = 0.f, az = 0.f, aw = 0.f;

    int i0 = g_csrc[beg];
    int i1 = (beg + 1 < end) ? g_csrc[beg + 1] : 0;
    float4 x0 = *reinterpret_cast<const float4*>(&g_xl1[(size_t)i0 * D1 + f0]);
    float4 x1 = *reinterpret_cast<const float4*>(&g_xl1[(size_t)i1 * D1 + f0]);

    for (int j = beg; j < end; j++) {
        int i2 = (j + 2 < end) ? g_csrc[j + 2] : 0;
        const float4 x2 = *reinterpret_cast<const float4*>(&g_xl1[(size_t)i2 * D1 + f0]);

        float s = lrelu(x0.x + xr4.x) * a4.x
                + lrelu(x0.y + xr4.y) * a4.y
                + lrelu(x0.z + xr4.z) * a4.z
                + lrelu(x0.w + xr4.w) * a4.w;
        s += __shfl_xor_sync(0xffffffffu, s, 1);
        s += __shfl_xor_sync(0xffffffffu, s, 2);
        s += __shfl_xor_sync(0xffffffffu, s, 4);   // head logit (8-lane group)

        float nm = fmaxf(m, s);
        float scale = __expf(m - nm);
        float p = __expf(s - nm);
        den = den * scale + p;
        ax = ax * scale + p * x0.x;
        ay = ay * scale + p * x0.y;
        az = az * scale + p * x0.z;
        aw = aw * scale + p * x0.w;
        m = nm;
        x0 = x1; x1 = x2;
    }
    float inv = 1.f / den;
    const float4 b4 = __ldg(reinterpret_cast<const float4*>(&b1[f0]));
    float4 o;
    o.x = ax * inv + b4.x; o.x = (o.x > 0.f) ? o.x : (__expf(o.x) - 1.f);
    o.y = ay * inv + b4.y; o.y = (o.y > 0.f) ? o.y : (__expf(o.y) - 1.f);
    o.z = az * inv + b4.z; o.z = (o.z > 0.f) ? o.z : (__expf(o.z) - 1.f);
    o.w = aw * inv + b4.w; o.w = (o.w > 0.f) ? o.w : (__expf(o.w) - 1.f);
    *reinterpret_cast<float4*>(&g_h[(size_t)n * D1 + f0]) = o;
}

// ---------------- layer 2 GEMM: xl2 = h@w2_l, xr2 = h@w2_r (f32x2) -------
#define TN2 32
#define G2T 160
__global__ __launch_bounds__(G2T) void gemm2_kernel(const float* __restrict__ wl,
                                                    const float* __restrict__ wr) {
    __shared__ float hs[TN2][D1];
    int n0 = blockIdx.x * TN2;
    int t = threadIdx.x;  // 0..159
    for (int idx = t; idx < TN2 * D1; idx += G2T) {
        int row = idx >> 7, col = idx & 127;
        int n = n0 + row;
        hs[row][col] = (n < NN) ? g_h[(size_t)n * D1 + col] : 0.f;
    }
    __syncthreads();
    int col = t % CLS;     // 0..39
    int q   = t / CLS;     // 0..3 -> rows q*8..q*8+7
    ull acc[8];
    #pragma unroll
    for (int r = 0; r < 8; r++) acc[r] = 0ull;
    for (int k = 0; k < D1; k++) {
        ull w2 = pk2(__ldg(&wl[k * CLS + col]), __ldg(&wr[k * CLS + col]));
        #pragma unroll
        for (int r = 0; r < 8; r++) {
            float hv = hs[q * 8 + r][k];
            acc[r] = fma2(pk2(hv, hv), w2, acc[r]);
        }
    }
    #pragma unroll
    for (int r = 0; r < 8; r++) {
        int n = n0 + q * 8 + r;
        if (n < NN) {
            float2 lr = upk2(acc[r]);
            g_xl2[(size_t)n * CLS + col] = lr.x;
            g_xr2[(size_t)n * CLS + col] = lr.y;
        }
    }
}

// ---------------- fused node kernel, layer 2 + log_softmax ---------------
__global__ void node2_kernel(const float* __restrict__ a2,
                             const float* __restrict__ b2,
                             float* __restrict__ out) {
    int n = (blockIdx.x * blockDim.x + threadIdx.x) >> 5;
    int lane = threadIdx.x & 31;
    if (n >= NN) return;
    bool act = (lane * 2) < CLS;
    int f0 = lane * 2;
    float2 xr2v = make_float2(0.f, 0.f), a2v = make_float2(0.f, 0.f);
    if (act) {
        xr2v = *reinterpret_cast<const float2*>(&g_xr2[(size_t)n * CLS + f0]);
        a2v  = __ldg(reinterpret_cast<const float2*>(&a2[f0]));
    }
    int beg = g_rowptr[n];
    int end = g_rowptr[n + 1];

    float m = -CUDART_INF_F, den = 0.f, ax = 0.f, ay = 0.f;

    int i0 = g_csrc[beg];
    int i1 = (beg + 1 < end) ? g_csrc[beg + 1] : 0;
    float2 x0 = act ? *reinterpret_cast<const float2*>(&g_xl2[(size_t)i0 * CLS + f0])
                    : make_float2(0.f, 0.f);
    float2 x1 = act ? *reinterpret_cast<const float2*>(&g_xl2[(size_t)i1 * CLS + f0])
                    : make_float2(0.f, 0.f);

    for (int j = beg; j < end; j++) {
        int i2 = (j + 2 < end) ? g_csrc[j + 2] : 0;
        const float2 x2 = act ? *reinterpret_cast<const float2*>(&g_xl2[(size_t)i2 * CLS + f0])
                              : make_float2(0.f, 0.f);

        float s = lrelu(x0.x + xr2v.x) * a2v.x + lrelu(x0.y + xr2v.y) * a2v.y;
        #pragma unroll
        for (int off = 16; off > 0; off >>= 1)
            s += __shfl_xor_sync(0xffffffffu, s, off);

        float nm = fmaxf(m, s);
        float scale = __expf(m - nm);
        float p = __expf(s - nm);
        den = den * scale + p;
        ax = ax * scale + p * x0.x;
        ay = ay * scale + p * x0.y;
        m = nm;
        x0 = x1; x1 = x2;
    }
    float inv = 1.f / den;
    float v0 = -CUDART_INF_F, v1 = -CUDART_INF_F;
    if (act) {
        v0 = ax * inv + __ldg(&b2[f0]);
        v1 = ay * inv + __ldg(&b2[f0 + 1]);
    }
    float mx = fmaxf(v0, v1);
    #pragma unroll
    for (int off = 16; off > 0; off >>= 1)
        mx = fmaxf(mx, __shfl_xor_sync(0xffffffffu, mx, off));
    float se = act ? (__expf(v0 - mx) + __expf(v1 - mx)) : 0.f;
    #pragma unroll
    for (int off = 16; off > 0; off >>= 1)
        se += __shfl_xor_sync(0xffffffffu, se, off);
    float lse = mx + logf(se);
    if (act) {
        float2 o = make_float2(v0 - lse, v1 - lse);
        *reinterpret_cast<float2*>(&out[(size_t)n * CLS + f0]) = o;
    }
}

// ---------------- launch ----------------
extern "C" void kernel_launch(void* const* d_in, const int* in_sizes, int n_in,
                              void* d_out, int out_size) {
    const float* x    = (const float*)d_in[0];
    const int*   eiw  = (const int*)d_in[1];   // int32 view (int32 or int64 data)
    const float* w1_l = (const float*)d_in[2];
    const float* w1_r = (const float*)d_in[3];
    const float* a1   = (const float*)d_in[4];
    const float* b1   = (const float*)d_in[5];
    const float* w2_l = (const float*)d_in[6];
    const float* w2_r = (const float*)d_in[7];
    const float* a2   = (const float*)d_in[8];
    const float* b2   = (const float*)d_in[9];
    float*       out  = (float*)d_out;

    // fork: CSR build on side stream, gemm1 on main stream
    cudaEventRecord(s_ev_fork, 0);
    cudaStreamWaitEvent(s_side, s_ev_fork, 0);

    detect_zero_kernel<<<(NN + 255) / 256, 256, 0, s_side>>>(eiw);
    conv_hist_kernel<<<(ET + 255) / 256, 256, 0, s_side>>>(eiw);
    scan1_kernel<<<NBLK, SCANB, 0, s_side>>>();
    scan2_kernel<<<1, 64, 0, s_side>>>();
    scan3_kernel<<<(NN + 255) / 256, 256, 0, s_side>>>();
    scatter_kernel<<<(ET + 255) / 256, 256, 0, s_side>>>();
    cudaEventRecord(s_ev_join, s_side);

    gemm1_kernel<<<(NN + TN1 - 1) / TN1, 128>>>(x, w1_l, w1_r);

    // join
    cudaStreamWaitEvent(0, s_ev_join, 0);

    node1_kernel<<<(NN * 32 + 255) / 256, 256>>>(a1, b1);
    gemm2_kernel<<<(NN + TN2 - 1) / TN2, G2T>>>(w2_l, w2_r);
    node2_kernel<<<(NN * 32 + 255) / 256, 256>>>(a2, b2, out);
}

// round 5
// speedup vs baseline: 2.9051x; 1.0237x over previous
#include <cuda_runtime.h>
#include <math.h>
#include <math_constants.h>

// Problem constants (fixed shapes per reference)
#define NN    50000                // nodes
#define NE    800000               // edges (without self loops)
#define ET    (NE + NN)            // edges + self loops
#define D1    128                  // HEADS*CH  (also F_IN)
#define HEADS 4
#define CH    32
#define CLS   40
#define SCANB 1024
#define NBLK  ((NN + SCANB - 1) / SCANB)   // 49
#define NHALF 25600                        // node1/gemm2 pipeline split (mult of 256)

typedef unsigned long long ull;

// ---------------- scratch (static device allocations) ----------------
static __device__ float g_xl1[(size_t)NN * D1];
static __device__ float g_xr1[(size_t)NN * D1];
static __device__ float g_h  [(size_t)NN * D1];
static __device__ float g_xl2[(size_t)NN * CLS];
static __device__ float g_xr2[(size_t)NN * CLS];
static __device__ int   g_src[ET];
static __device__ int   g_dst[ET];
static __device__ int   g_deg[NN];
static __device__ int   g_incl[NBLK * SCANB];
static __device__ int   g_bsum[NBLK];
static __device__ int   g_boff[NBLK];
static __device__ int   g_rowptr[NN + 1];
static __device__ int   g_cursor[NN];
static __device__ int   g_csrc[ET];
static __device__ int   g_is64;

// ---------------- stream/event objects (created at process start) -------
static cudaStream_t s_side;
static cudaEvent_t  s_ev_fork;
static cudaEvent_t  s_ev_join;
static cudaEvent_t  s_ev_h;     // node1 first half done
static cudaEvent_t  s_ev_g2a;   // gemm2 first half done
namespace {
struct StreamInit {
    StreamInit() {
        cudaStreamCreateWithFlags(&s_side, cudaStreamNonBlocking);
        cudaEventCreateWithFlags(&s_ev_fork, cudaEventDisableTiming);
        cudaEventCreateWithFlags(&s_ev_join, cudaEventDisableTiming);
        cudaEventCreateWithFlags(&s_ev_h, cudaEventDisableTiming);
        cudaEventCreateWithFlags(&s_ev_g2a, cudaEventDisableTiming);
    }
};
static StreamInit s_stream_init;
}

// ---------------- f32x2 helpers (Blackwell packed fp32) ----------------
__device__ __forceinline__ ull pk2(float a, float b) {
    ull r;
    asm("mov.b64 %0, {%1,%2};" : "=l"(r) : "f"(a), "f"(b));
    return r;
}
__device__ __forceinline__ ull fma2(ull a, ull b, ull c) {
    ull d;
    asm("fma.rn.f32x2 %0, %1, %2, %3;" : "=l"(d) : "l"(a), "l"(b), "l"(c));
    return d;
}
__device__ __forceinline__ float2 upk2(ull v) {
    float2 f;
    asm("mov.b64 {%0,%1}, %2;" : "=f"(f.x), "=f"(f.y) : "l"(v));
    return f;
}

__device__ __forceinline__ float lrelu(float v) {
    return (v > 0.f) ? v : 0.2f * v;
}

// ---------------- CSR build -------------------------------------------
__global__ void detect_zero_kernel(const int* __restrict__ w) {
    int i = blockIdx.x * blockDim.x + threadIdx.x;
    if (i < NN) g_deg[i] = 0;
    if (blockIdx.x == 0) {
        __shared__ int any_nonzero;
        if (threadIdx.x == 0) any_nonzero = 0;
        __syncthreads();
        int local = 0;
        for (int k = threadIdx.x; k < 4096; k += blockDim.x)
            if (w[2 * k + 1] != 0) local = 1;
        if (local) atomicOr(&any_nonzero, 1);
        __syncthreads();
        if (threadIdx.x == 0) g_is64 = any_nonzero ? 0 : 1;
    }
}

__global__ void conv_hist_kernel(const int* __restrict__ w) {
    int e = blockIdx.x * blockDim.x + threadIdx.x;
    if (e >= ET) return;
    int src, dst;
    if (e >= NE) {
        src = e - NE; dst = src;
    } else if (g_is64) {
        src = w[2 * e];
        dst = w[2 * (NE + e)];
    } else {
        src = w[e];
        dst = w[NE + e];
    }
    g_src[e] = src;
    g_dst[e] = dst;
    atomicAdd(&g_deg[dst], 1);
}

__global__ void scan1_kernel() {
    __shared__ int sm[SCANB];
    int t = threadIdx.x;
    int i = blockIdx.x * SCANB + t;
    sm[t] = (i < NN) ? g_deg[i] : 0;
    __syncthreads();
    for (int off = 1; off < SCANB; off <<= 1) {
        int add = (t >= off) ? sm[t - off] : 0;
        __syncthreads();
        sm[t] += add;
        __syncthreads();
    }
    g_incl[i] = sm[t];
    if (t == SCANB - 1) g_bsum[blockIdx.x] = sm[t];
}

__global__ void scan2_kernel() {
    __shared__ int sm[64];
    int t = threadIdx.x;  // 64 threads
    int v = (t < NBLK) ? g_bsum[t] : 0;
    sm[t] = v;
    __syncthreads();
    #pragma unroll
    for (int off = 1; off < 64; off <<= 1) {
        int add = (t >= off) ? sm[t - off] : 0;
        __syncthreads();
        sm[t] += add;
        __syncthreads();
    }
    if (t < NBLK) g_boff[t] = sm[t] - v;   // exclusive
}

__global__ void scan3_kernel() {
    int i = blockIdx.x * blockDim.x + threadIdx.x;
    if (i >= NN) return;
    int incl = g_incl[i] + g_boff[i >> 10];
    g_rowptr[i + 1] = incl;
    g_cursor[i] = incl - g_deg[i];
    if (i == 0) g_rowptr[0] = 0;
}

__global__ void scatter_kernel() {
    int e = blockIdx.x * blockDim.x + threadIdx.x;
    if (e >= ET) return;
    int dst = g_dst[e];
    int pos = atomicAdd(&g_cursor[dst], 1);
    g_csrc[pos] = g_src[e];
}

// ---------------- layer 1 GEMM: xl1 = x@w1_l, xr1 = x@w1_r (f32x2) -------
#define TN1 32
__global__ __launch_bounds__(128) void gemm1_kernel(const float* __restrict__ x,
                                                    const float* __restrict__ wl,
                                                    const float* __restrict__ wr) {
    __shared__ float xs[TN1][D1];
    int n0 = blockIdx.x * TN1;
    int t = threadIdx.x;  // 0..127
    #pragma unroll
    for (int i = 0; i < TN1; i++) {
        int n = n0 + i;
        xs[i][t] = (n < NN) ? x[(size_t)n * D1 + t] : 0.f;
    }
    __syncthreads();
    const int r0 = (t >> 6) * 16;   // rows r0..r0+15
    const int c  = (t & 63) * 2;    // columns c, c+1
    ull accA[16], accB[16];
    #pragma unroll
    for (int i = 0; i < 16; i++) { accA[i] = 0ull; accB[i] = 0ull; }
    for (int k = 0; k < D1; k += 4) {
        ull wa[4], wb[4];
        #pragma unroll
        for (int kk = 0; kk < 4; kk++) {
            wa[kk] = pk2(__ldg(&wl[(k + kk) * D1 + c]),     __ldg(&wr[(k + kk) * D1 + c]));
            wb[kk] = pk2(__ldg(&wl[(k + kk) * D1 + c + 1]), __ldg(&wr[(k + kk) * D1 + c + 1]));
        }
        #pragma unroll
        for (int i = 0; i < 16; i++) {
            const float4 xv = *reinterpret_cast<const float4*>(&xs[r0 + i][k]);
            ull xp;
            xp = pk2(xv.x, xv.x); accA[i] = fma2(xp, wa[0], accA[i]); accB[i] = fma2(xp, wb[0], accB[i]);
            xp = pk2(xv.y, xv.y); accA[i] = fma2(xp, wa[1], accA[i]); accB[i] = fma2(xp, wb[1], accB[i]);
            xp = pk2(xv.z, xv.z); accA[i] = fma2(xp, wa[2], accA[i]); accB[i] = fma2(xp, wb[2], accB[i]);
            xp = pk2(xv.w, xv.w); accA[i] = fma2(xp, wa[3], accA[i]); accB[i] = fma2(xp, wb[3], accB[i]);
        }
    }
    #pragma unroll
    for (int i = 0; i < 16; i++) {
        int n = n0 + r0 + i;
        if (n < NN) {
            float2 A = upk2(accA[i]);   // (l[c], r[c])
            float2 B = upk2(accB[i]);   // (l[c+1], r[c+1])
            *reinterpret_cast<float2*>(&g_xl1[(size_t)n * D1 + c]) = make_float2(A.x, B.x);
            *reinterpret_cast<float2*>(&g_xr1[(size_t)n * D1 + c]) = make_float2(A.y, B.y);
        }
    }
}

// ---------------- fused node kernel, layer 1 -----------------------------
// One warp per dst node. No max-tracking (logits bounded, exp-safe).
// 2-wide edge unroll, depth-4 gather pipeline.
__global__ void node1_kernel(const float* __restrict__ a1,
                             const float* __restrict__ b1,
                             int nbeg, int nend) {
    int n = nbeg + ((blockIdx.x * blockDim.x + threadIdx.x) >> 5);
    int lane = threadIdx.x & 31;
    if (n >= nend) return;
    int f0 = lane * 4;
    const float4 xr4 = *reinterpret_cast<const float4*>(&g_xr1[(size_t)n * D1 + f0]);
    const float4 a4  = __ldg(reinterpret_cast<const float4*>(&a1[f0]));
    int beg = g_rowptr[n];
    int cnt = g_rowptr[n + 1] - beg;       // >= 1 (self loop)
    const int* cs = g_csrc + beg;

    float den0 = 0.f, den1 = 0.f;
    float ax = 0.f, ay = 0.f, az = 0.f, aw = 0.f;

    int idx0 = cs[0];
    int idx1 = (1 < cnt) ? cs[1] : 0;
    int idx2 = (2 < cnt) ? cs[2] : 0;
    int idx3 = (3 < cnt) ? cs[3] : 0;
    float4 x0 = *reinterpret_cast<const float4*>(&g_xl1[(size_t)idx0 * D1 + f0]);
    float4 x1 = *reinterpret_cast<const float4*>(&g_xl1[(size_t)idx1 * D1 + f0]);
    float4 x2 = *reinterpret_cast<const float4*>(&g_xl1[(size_t)idx2 * D1 + f0]);
    float4 x3 = *reinterpret_cast<const float4*>(&g_xl1[(size_t)idx3 * D1 + f0]);

    int j = 0;
    for (; j + 1 < cnt; j += 2) {
        int i4 = (j + 4 < cnt) ? cs[j + 4] : 0;
        int i5 = (j + 5 < cnt) ? cs[j + 5] : 0;
        const float4 nx0 = *reinterpret_cast<const float4*>(&g_xl1[(size_t)i4 * D1 + f0]);
        const float4 nx1 = *reinterpret_cast<const float4*>(&g_xl1[(size_t)i5 * D1 + f0]);

        float s0 = lrelu(x0.x + xr4.x) * a4.x
                 + lrelu(x0.y + xr4.y) * a4.y
                 + lrelu(x0.z + xr4.z) * a4.z
                 + lrelu(x0.w + xr4.w) * a4.w;
        float s1 = lrelu(x1.x + xr4.x) * a4.x
                 + lrelu(x1.y + xr4.y) * a4.y
                 + lrelu(x1.z + xr4.z) * a4.z
                 + lrelu(x1.w + xr4.w) * a4.w;
        s0 += __shfl_xor_sync(0xffffffffu, s0, 1);
        s1 += __shfl_xor_sync(0xffffffffu, s1, 1);
        s0 += __shfl_xor_sync(0xffffffffu, s0, 2);
        s1 += __shfl_xor_sync(0xffffffffu, s1, 2);
        s0 += __shfl_xor_sync(0xffffffffu, s0, 4);
        s1 += __shfl_xor_sync(0xffffffffu, s1, 4);
        float p0 = __expf(s0);
        float p1 = __expf(s1);
        den0 += p0; den1 += p1;
        ax = fmaf(p0, x0.x, ax); ay = fmaf(p0, x0.y, ay);
        az = fmaf(p0, x0.z, az); aw = fmaf(p0, x0.w, aw);
        ax = fmaf(p1, x1.x, ax); ay = fmaf(p1, x1.y, ay);
        az = fmaf(p1, x1.z, az); aw = fmaf(p1, x1.w, aw);
        x0 = x2; x1 = x3; x2 = nx0; x3 = nx1;
    }
    if (j < cnt) {  // tail edge
        float s0 = lrelu(x0.x + xr4.x) * a4.x
                 + lrelu(x0.y + xr4.y) * a4.y
                 + lrelu(x0.z + xr4.z) * a4.z
                 + lrelu(x0.w + xr4.w) * a4.w;
        s0 += __shfl_xor_sync(0xffffffffu, s0, 1);
        s0 += __shfl_xor_sync(0xffffffffu, s0, 2);
        s0 += __shfl_xor_sync(0xffffffffu, s0, 4);
        float p0 = __expf(s0);
        den0 += p0;
        ax = fmaf(p0, x0.x, ax); ay = fmaf(p0, x0.y, ay);
        az = fmaf(p0, x0.z, az); aw = fmaf(p0, x0.w, aw);
    }
    float inv = 1.f / (den0 + den1);
    const float4 b4 = __ldg(reinterpret_cast<const float4*>(&b1[f0]));
    float4 o;
    o.x = ax * inv + b4.x; o.x = (o.x > 0.f) ? o.x : (__expf(o.x) - 1.f);
    o.y = ay * inv + b4.y; o.y = (o.y > 0.f) ? o.y : (__expf(o.y) - 1.f);
    o.z = az * inv + b4.z; o.z = (o.z > 0.f) ? o.z : (__expf(o.z) - 1.f);
    o.w = aw * inv + b4.w; o.w = (o.w > 0.f) ? o.w : (__expf(o.w) - 1.f);
    *reinterpret_cast<float4*>(&g_h[(size_t)n * D1 + f0]) = o;
}

// ---------------- layer 2 GEMM: xl2 = h@w2_l, xr2 = h@w2_r (f32x2) -------
#define TN2 32
#define G2T 160
__global__ __launch_bounds__(G2T) void gemm2_kernel(const float* __restrict__ wl,
                                                    const float* __restrict__ wr,
                                                    int nbeg, int nend) {
    __shared__ float hs[TN2][D1];
    int n0 = nbeg + blockIdx.x * TN2;
    int t = threadIdx.x;  // 0..159
    for (int idx = t; idx < TN2 * D1; idx += G2T) {
        int row = idx >> 7, col = idx & 127;
        int n = n0 + row;
        hs[row][col] = (n < nend) ? g_h[(size_t)n * D1 + col] : 0.f;
    }
    __syncthreads();
    int col = t % CLS;     // 0..39
    int q   = t / CLS;     // 0..3 -> rows q*8..q*8+7
    ull acc[8];
    #pragma unroll
    for (int r = 0; r < 8; r++) acc[r] = 0ull;
    for (int k = 0; k < D1; k++) {
        ull w2 = pk2(__ldg(&wl[k * CLS + col]), __ldg(&wr[k * CLS + col]));
        #pragma unroll
        for (int r = 0; r < 8; r++) {
            float hv = hs[q * 8 + r][k];
            acc[r] = fma2(pk2(hv, hv), w2, acc[r]);
        }
    }
    #pragma unroll
    for (int r = 0; r < 8; r++) {
        int n = n0 + q * 8 + r;
        if (n < nend) {
            float2 lr = upk2(acc[r]);
            g_xl2[(size_t)n * CLS + col] = lr.x;
            g_xr2[(size_t)n * CLS + col] = lr.y;
        }
    }
}

// ---------------- fused node kernel, layer 2 + log_softmax ---------------
// No max-tracking; 2-wide unroll, depth-4 pipeline.
__global__ void node2_kernel(const float* __restrict__ a2,
                             const float* __restrict__ b2,
                             float* __restrict__ out) {
    int n = (blockIdx.x * blockDim.x + threadIdx.x) >> 5;
    int lane = threadIdx.x & 31;
    if (n >= NN) return;
    bool act = (lane * 2) < CLS;
    int f0 = lane * 2;
    float2 xr2v = make_float2(0.f, 0.f), a2v = make_float2(0.f, 0.f);
    if (act) {
        xr2v = *reinterpret_cast<const float2*>(&g_xr2[(size_t)n * CLS + f0]);
        a2v  = __ldg(reinterpret_cast<const float2*>(&a2[f0]));
    }
    int beg = g_rowptr[n];
    int cnt = g_rowptr[n + 1] - beg;
    const int* cs = g_csrc + beg;

    float den0 = 0.f, den1 = 0.f, ax = 0.f, ay = 0.f;

    int idx0 = cs[0];
    int idx1 = (1 < cnt) ? cs[1] : 0;
    int idx2 = (2 < cnt) ? cs[2] : 0;
    int idx3 = (3 < cnt) ? cs[3] : 0;
    float2 zero2 = make_float2(0.f, 0.f);
    float2 x0 = act ? *reinterpret_cast<const float2*>(&g_xl2[(size_t)idx0 * CLS + f0]) : zero2;
    float2 x1 = act ? *reinterpret_cast<const float2*>(&g_xl2[(size_t)idx1 * CLS + f0]) : zero2;
    float2 x2 = act ? *reinterpret_cast<const float2*>(&g_xl2[(size_t)idx2 * CLS + f0]) : zero2;
    float2 x3 = act ? *reinterpret_cast<const float2*>(&g_xl2[(size_t)idx3 * CLS + f0]) : zero2;

    int j = 0;
    for (; j + 1 < cnt; j += 2) {
        int i4 = (j + 4 < cnt) ? cs[j + 4] : 0;
        int i5 = (j + 5 < cnt) ? cs[j + 5] : 0;
        const float2 nx0 = act ? *reinterpret_cast<const float2*>(&g_xl2[(size_t)i4 * CLS + f0]) : zero2;
        const float2 nx1 = act ? *reinterpret_cast<const float2*>(&g_xl2[(size_t)i5 * CLS + f0]) : zero2;

        float s0 = lrelu(x0.x + xr2v.x) * a2v.x + lrelu(x0.y + xr2v.y) * a2v.y;
        float s1 = lrelu(x1.x + xr2v.x) * a2v.x + lrelu(x1.y + xr2v.y) * a2v.y;
        #pragma unroll
        for (int off = 16; off > 0; off >>= 1) {
            s0 += __shfl_xor_sync(0xffffffffu, s0, off);
            s1 += __shfl_xor_sync(0xffffffffu, s1, off);
        }
        float p0 = __expf(s0);
        float p1 = __expf(s1);
        den0 += p0; den1 += p1;
        ax = fmaf(p0, x0.x, ax); ay = fmaf(p0, x0.y, ay);
        ax = fmaf(p1, x1.x, ax); ay = fmaf(p1, x1.y, ay);
        x0 = x2; x1 = x3; x2 = nx0; x3 = nx1;
    }
    if (j < cnt) {
        float s0 = lrelu(x0.x + xr2v.x) * a2v.x + lrelu(x0.y + xr2v.y) * a2v.y;
        #pragma unroll
        for (int off = 16; off > 0; off >>= 1)
            s0 += __shfl_xor_sync(0xffffffffu, s0, off);
        float p0 = __expf(s0);
        den0 += p0;
        ax = fmaf(p0, x0.x, ax); ay = fmaf(p0, x0.y, ay);
    }
    float inv = 1.f / (den0 + den1);
    float v0 = -CUDART_INF_F, v1 = -CUDART_INF_F;
    if (act) {
        v0 = ax * inv + __ldg(&b2[f0]);
        v1 = ay * inv + __ldg(&b2[f0 + 1]);
    }
    float mx = fmaxf(v0, v1);
    #pragma unroll
    for (int off = 16; off > 0; off >>= 1)
        mx = fmaxf(mx, __shfl_xor_sync(0xffffffffu, mx, off));
    float se = act ? (__expf(v0 - mx) + __expf(v1 - mx)) : 0.f;
    #pragma unroll
    for (int off = 16; off > 0; off >>= 1)
        se += __shfl_xor_sync(0xffffffffu, se, off);
    float lse = mx + logf(se);
    if (act) {
        float2 o = make_float2(v0 - lse, v1 - lse);
        *reinterpret_cast<float2*>(&out[(size_t)n * CLS + f0]) = o;
    }
}

// ---------------- launch ----------------
extern "C" void kernel_launch(void* const* d_in, const int* in_sizes, int n_in,
                              void* d_out, int out_size) {
    const float* x    = (const float*)d_in[0];
    const int*   eiw  = (const int*)d_in[1];   // int32 view (int32 or int64 data)
    const float* w1_l = (const float*)d_in[2];
    const float* w1_r = (const float*)d_in[3];
    const float* a1   = (const float*)d_in[4];
    const float* b1   = (const float*)d_in[5];
    const float* w2_l = (const float*)d_in[6];
    const float* w2_r = (const float*)d_in[7];
    const float* a2   = (const float*)d_in[8];
    const float* b2   = (const float*)d_in[9];
    float*       out  = (float*)d_out;

    // fork: CSR build on side stream, gemm1 on main stream
    cudaEventRecord(s_ev_fork, 0);
    cudaStreamWaitEvent(s_side, s_ev_fork, 0);

    detect_zero_kernel<<<(NN + 255) / 256, 256, 0, s_side>>>(eiw);
    conv_hist_kernel<<<(ET + 255) / 256, 256, 0, s_side>>>(eiw);
    scan1_kernel<<<NBLK, SCANB, 0, s_side>>>();
    scan2_kernel<<<1, 64, 0, s_side>>>();
    scan3_kernel<<<(NN + 255) / 256, 256, 0, s_side>>>();
    scatter_kernel<<<(ET + 255) / 256, 256, 0, s_side>>>();
    cudaEventRecord(s_ev_join, s_side);

    gemm1_kernel<<<(NN + TN1 - 1) / TN1, 128>>>(x, w1_l, w1_r);

    // join CSR
    cudaStreamWaitEvent(0, s_ev_join, 0);

    // node1 first half, then second half; gemm2 first half overlaps node1 b
    node1_kernel<<<(NHALF * 32) / 256, 256>>>(a1, b1, 0, NHALF);
    cudaEventRecord(s_ev_h, 0);
    cudaStreamWaitEvent(s_side, s_ev_h, 0);
    gemm2_kernel<<<NHALF / TN2, G2T, 0, s_side>>>(w2_l, w2_r, 0, NHALF);
    cudaEventRecord(s_ev_g2a, s_side);

    node1_kernel<<<((NN - NHALF) * 32 + 255) / 256, 256>>>(a1, b1, NHALF, NN);
    gemm2_kernel<<<(NN - NHALF + TN2 - 1) / TN2, G2T>>>(w2_l, w2_r, NHALF, NN);

    cudaStreamWaitEvent(0, s_ev_g2a, 0);
    node2_kernel<<<(NN * 32 + 255) / 256, 256>>>(a2, b2, out);
}

// round 7
// speedup vs baseline: 3.2648x; 1.1238x over previous
#include <cuda_runtime.h>
#include <cuda_bf16.h>
#include <math.h>
#include <math_constants.h>
#include <cstdint>

// Problem constants (fixed shapes per reference)
#define NN    50000                // nodes
#define NE    800000               // edges (without self loops)
#define ET    (NE + NN)            // edges + self loops
#define D1    128                  // HEADS*CH  (also F_IN)
#define HEADS 4
#define CH    32
#define CLS   40
#define SCANB 1024
#define NBLK  ((NN + SCANB - 1) / SCANB)   // 49
#define NHALF 25600                        // node1/gemm2 pipeline split

typedef unsigned long long ull;

// ---------------- scratch (static device allocations) ----------------
static __device__ float g_xl1[(size_t)NN * D1];
static __device__ float g_xr1[(size_t)NN * D1];
static __device__ float g_h  [(size_t)NN * D1];
static __device__ float g_xl2[(size_t)NN * CLS];
static __device__ float g_xr2[(size_t)NN * CLS];
static __device__ int   g_src[ET];
static __device__ int   g_dst[ET];
static __device__ int   g_deg[NN];
static __device__ int   g_incl[NBLK * SCANB];
static __device__ int   g_bsum[NBLK];
static __device__ int   g_boff[NBLK];
static __device__ int   g_rowptr[NN + 1];
static __device__ int   g_cursor[NN];
static __device__ int   g_csrc[ET];
static __device__ int   g_is64;
// split-bf16 weight tiles, [n][k] layout (n = output col, k contiguous)
static __device__ __nv_bfloat16 g_wlh[128 * 128];
static __device__ __nv_bfloat16 g_wll[128 * 128];
static __device__ __nv_bfloat16 g_wrh[128 * 128];
static __device__ __nv_bfloat16 g_wrl[128 * 128];

// ---------------- f32x2 helpers (Blackwell packed fp32) ----------------
__device__ __forceinline__ ull pk2(float a, float b) {
    ull r;
    asm("mov.b64 %0, {%1,%2};" : "=l"(r) : "f"(a), "f"(b));
    return r;
}
__device__ __forceinline__ ull fma2(ull a, ull b, ull c) {
    ull d;
    asm("fma.rn.f32x2 %0, %1, %2, %3;" : "=l"(d) : "l"(a), "l"(b), "l"(c));
    return d;
}
__device__ __forceinline__ float2 upk2(ull v) {
    float2 f;
    asm("mov.b64 {%0,%1}, %2;" : "=f"(f.x), "=f"(f.y) : "l"(v));
    return f;
}
__device__ __forceinline__ float lrelu(float v) {
    return (v > 0.f) ? v : 0.2f * v;
}

// ---------------- mma.sync helpers ----------------
#define MMA_BF16(d, a, b0, b1)                                                 \
    asm volatile("mma.sync.aligned.m16n8k16.row.col.f32.bf16.bf16.f32 "        \
        "{%0,%1,%2,%3}, {%4,%5,%6,%7}, {%8,%9}, {%0,%1,%2,%3};"                \
        : "+f"((d)[0]), "+f"((d)[1]), "+f"((d)[2]), "+f"((d)[3])               \
        : "r"((a)[0]), "r"((a)[1]), "r"((a)[2]), "r"((a)[3]), "r"(b0), "r"(b1))

// split fp32 pair into packed bf16x2 hi and lo
__device__ __forceinline__ void split2(float2 p, uint32_t& hi, uint32_t& lo) {
    __nv_bfloat16 hx = __float2bfloat16(p.x);
    __nv_bfloat16 hy = __float2bfloat16(p.y);
    __nv_bfloat16 lx = __float2bfloat16(p.x - __bfloat162float(hx));
    __nv_bfloat16 ly = __float2bfloat16(p.y - __bfloat162float(hy));
    __nv_bfloat162 h2(hx, hy), l2(lx, ly);
    hi = *reinterpret_cast<uint32_t*>(&h2);
    lo = *reinterpret_cast<uint32_t*>(&l2);
}

// ---------------- CSR build -------------------------------------------
__global__ void detect_zero_kernel(const int* __restrict__ w) {
    int i = blockIdx.x * blockDim.x + threadIdx.x;
    if (i < NN) g_deg[i] = 0;
    if (blockIdx.x == 0) {
        __shared__ int any_nonzero;
        if (threadIdx.x == 0) any_nonzero = 0;
        __syncthreads();
        int local = 0;
        for (int k = threadIdx.x; k < 4096; k += blockDim.x)
            if (w[2 * k + 1] != 0) local = 1;
        if (local) atomicOr(&any_nonzero, 1);
        __syncthreads();
        if (threadIdx.x == 0) g_is64 = any_nonzero ? 0 : 1;
    }
}

__global__ void conv_hist_kernel(const int* __restrict__ w) {
    int e = blockIdx.x * blockDim.x + threadIdx.x;
    if (e >= ET) return;
    int src, dst;
    if (e >= NE) {
        src = e - NE; dst = src;
    } else if (g_is64) {
        src = w[2 * e];
        dst = w[2 * (NE + e)];
    } else {
        src = w[e];
        dst = w[NE + e];
    }
    g_src[e] = src;
    g_dst[e] = dst;
    atomicAdd(&g_deg[dst], 1);
}

__global__ void scan1_kernel() {
    __shared__ int sm[SCANB];
    int t = threadIdx.x;
    int i = blockIdx.x * SCANB + t;
    sm[t] = (i < NN) ? g_deg[i] : 0;
    __syncthreads();
    for (int off = 1; off < SCANB; off <<= 1) {
        int add = (t >= off) ? sm[t - off] : 0;
        __syncthreads();
        sm[t] += add;
        __syncthreads();
    }
    g_incl[i] = sm[t];
    if (t == SCANB - 1) g_bsum[blockIdx.x] = sm[t];
}

__global__ void scan2_kernel() {
    __shared__ int sm[64];
    int t = threadIdx.x;
    int v = (t < NBLK) ? g_bsum[t] : 0;
    sm[t] = v;
    __syncthreads();
    #pragma unroll
    for (int off = 1; off < 64; off <<= 1) {
        int add = (t >= off) ? sm[t - off] : 0;
        __syncthreads();
        sm[t] += add;
        __syncthreads();
    }
    if (t < NBLK) g_boff[t] = sm[t] - v;
}

__global__ void scan3_kernel() {
    int i = blockIdx.x * blockDim.x + threadIdx.x;
    if (i >= NN) return;
    int incl = g_incl[i] + g_boff[i >> 10];
    g_rowptr[i + 1] = incl;
    g_cursor[i] = incl - g_deg[i];
    if (i == 0) g_rowptr[0] = 0;
}

__global__ void scatter_kernel() {
    int e = blockIdx.x * blockDim.x + threadIdx.x;
    if (e >= ET) return;
    int dst = g_dst[e];
    int pos = atomicAdd(&g_cursor[dst], 1);
    g_csrc[pos] = g_src[e];
}

// ---------------- weight prep: fp32 [k][n] -> split bf16 [n][k] ---------
__global__ void wprep_kernel(const float* __restrict__ wl,
                             const float* __restrict__ wr) {
    int i = blockIdx.x * blockDim.x + threadIdx.x;
    if (i >= 128 * 128) return;
    int k = i >> 7, n = i & 127;
    int o = n * 128 + k;
    float vl = wl[i];
    __nv_bfloat16 hl = __float2bfloat16(vl);
    g_wlh[o] = hl;
    g_wll[o] = __float2bfloat16(vl - __bfloat162float(hl));
    float vr = wr[i];
    __nv_bfloat16 hr = __float2bfloat16(vr);
    g_wrh[o] = hr;
    g_wrl[o] = __float2bfloat16(vr - __bfloat162float(hr));
}

// ---------------- layer 1 GEMM via mma.sync bf16 (split, fp32 accum) ----
// 512 threads = 16 warps. Warp wid: m-tile = (wid&7) -> rows 16*(wid&7)..+15,
// n-half = wid>>3 -> cols 64*(wid>>3)..+63. Block = 128 rows x 128 cols,
// looped over 2 weight matrices.
#define BROW_BYTES 272        // 136 bf16; 68 words -> conflict-free frag loads
#define BTILE_BYTES (128 * BROW_BYTES)
#define G1_SMEM (4 * BTILE_BYTES)

__global__ __launch_bounds__(512) void gemm1_mma_kernel(const float* __restrict__ x) {
    extern __shared__ char smc[];
    // stage 4 weight tiles into SMEM with padded stride
    {
        const __nv_bfloat16* gsrc[4] = {g_wlh, g_wll, g_wrh, g_wrl};
        #pragma unroll
        for (int tsel = 0; tsel < 4; tsel++) {
            const uint4* s = reinterpret_cast<const uint4*>(gsrc[tsel]);
            char* d = smc + tsel * BTILE_BYTES;
            for (int j = threadIdx.x; j < 128 * 16; j += 512) {
                int row = j >> 4, q = j & 15;
                *reinterpret_cast<uint4*>(d + row * BROW_BYTES + q * 16) = s[j];
            }
        }
    }

    int lane = threadIdx.x & 31, wid = threadIdx.x >> 5;
    int g = lane >> 2, tg = lane & 3;
    int mw = wid & 7, nh = wid >> 3;
    int rowg  = blockIdx.x * 128 + mw * 16 + g;
    int rowg8 = rowg + 8;
    int r0 = (rowg  < NN) ? rowg  : (NN - 1);
    int r8 = (rowg8 < NN) ? rowg8 : (NN - 1);
    const float* xr0 = x + (size_t)r0 * D1;
    const float* xr8 = x + (size_t)r8 * D1;

    // A fragments for all 8 k-chunks (hi and lo)
    uint32_t ah[8][4], al[8][4];
    #pragma unroll
    for (int kc = 0; kc < 8; kc++) {
        int k0 = kc * 16 + 2 * tg;
        float2 p0 = *reinterpret_cast<const float2*>(xr0 + k0);
        float2 p1 = *reinterpret_cast<const float2*>(xr8 + k0);
        float2 p2 = *reinterpret_cast<const float2*>(xr0 + k0 + 8);
        float2 p3 = *reinterpret_cast<const float2*>(xr8 + k0 + 8);
        split2(p0, ah[kc][0], al[kc][0]);
        split2(p1, ah[kc][1], al[kc][1]);
        split2(p2, ah[kc][2], al[kc][2]);
        split2(p3, ah[kc][3], al[kc][3]);
    }
    __syncthreads();

    #pragma unroll
    for (int wsel = 0; wsel < 2; wsel++) {
        const char* BH = smc + (wsel * 2 + 0) * BTILE_BYTES;
        const char* BL = smc + (wsel * 2 + 1) * BTILE_BYTES;
        float acc[8][4];
        #pragma unroll
        for (int nt = 0; nt < 8; nt++)
            acc[nt][0] = acc[nt][1] = acc[nt][2] = acc[nt][3] = 0.f;

        #pragma unroll
        for (int kc = 0; kc < 8; kc++) {
            int kb = kc * 32 + tg * 4;   // byte offset of k-pair within row
            #pragma unroll
            for (int nt = 0; nt < 8; nt++) {
                int nrow = nh * 64 + nt * 8 + g;
                const char* ph = BH + nrow * BROW_BYTES + kb;
                const char* pl = BL + nrow * BROW_BYTES + kb;
                uint32_t bh0 = *reinterpret_cast<const uint32_t*>(ph);
                uint32_t bh1 = *reinterpret_cast<const uint32_t*>(ph + 16);
                uint32_t bl0 = *reinterpret_cast<const uint32_t*>(pl);
                uint32_t bl1 = *reinterpret_cast<const uint32_t*>(pl + 16);
                MMA_BF16(acc[nt], ah[kc], bh0, bh1);
                MMA_BF16(acc[nt], al[kc], bh0, bh1);
                MMA_BF16(acc[nt], ah[kc], bl0, bl1);
            }
        }
        float* dst = wsel ? g_xr1 : g_xl1;
        #pragma unroll
        for (int nt = 0; nt < 8; nt++) {
            int col = nh * 64 + nt * 8 + 2 * tg;
            if (rowg < NN)
                *reinterpret_cast<float2*>(dst + (size_t)rowg * D1 + col) =
                    make_float2(acc[nt][0], acc[nt][1]);
            if (rowg8 < NN)
                *reinterpret_cast<float2*>(dst + (size_t)rowg8 * D1 + col) =
                    make_float2(acc[nt][2], acc[nt][3]);
        }
    }
}

// ---------------- fused node kernel, layer 1 -----------------------------
__global__ void node1_kernel(const float* __restrict__ a1,
                             const float* __restrict__ b1,
                             int nbeg, int nend) {
    int n = nbeg + ((blockIdx.x * blockDim.x + threadIdx.x) >> 5);
    int lane = threadIdx.x & 31;
    if (n >= nend) return;
    int f0 = lane * 4;
    const float4 xr4 = *reinterpret_cast<const float4*>(&g_xr1[(size_t)n * D1 + f0]);
    const float4 a4  = __ldg(reinterpret_cast<const float4*>(&a1[f0]));
    int beg = g_rowptr[n];
    int cnt = g_rowptr[n + 1] - beg;
    const int* cs = g_csrc + beg;

    float den0 = 0.f, den1 = 0.f;
    float ax = 0.f, ay = 0.f, az = 0.f, aw = 0.f;

    int idx0 = cs[0];
    int idx1 = (1 < cnt) ? cs[1] : 0;
    int idx2 = (2 < cnt) ? cs[2] : 0;
    int idx3 = (3 < cnt) ? cs[3] : 0;
    float4 x0 = *reinterpret_cast<const float4*>(&g_xl1[(size_t)idx0 * D1 + f0]);
    float4 x1 = *reinterpret_cast<const float4*>(&g_xl1[(size_t)idx1 * D1 + f0]);
    float4 x2 = *reinterpret_cast<const float4*>(&g_xl1[(size_t)idx2 * D1 + f0]);
    float4 x3 = *reinterpret_cast<const float4*>(&g_xl1[(size_t)idx3 * D1 + f0]);

    int j = 0;
    for (; j + 1 < cnt; j += 2) {
        int i4 = (j + 4 < cnt) ? cs[j + 4] : 0;
        int i5 = (j + 5 < cnt) ? cs[j + 5] : 0;
        const float4 nx0 = *reinterpret_cast<const float4*>(&g_xl1[(size_t)i4 * D1 + f0]);
        const float4 nx1 = *reinterpret_cast<const float4*>(&g_xl1[(size_t)i5 * D1 + f0]);

        float s0 = lrelu(x0.x + xr4.x) * a4.x
                 + lrelu(x0.y + xr4.y) * a4.y
                 + lrelu(x0.z + xr4.z) * a4.z
                 + lrelu(x0.w + xr4.w) * a4.w;
        float s1 = lrelu(x1.x + xr4.x) * a4.x
                 + lrelu(x1.y + xr4.y) * a4.y
                 + lrelu(x1.z + xr4.z) * a4.z
                 + lrelu(x1.w + xr4.w) * a4.w;
        s0 += __shfl_xor_sync(0xffffffffu, s0, 1);
        s1 += __shfl_xor_sync(0xffffffffu, s1, 1);
        s0 += __shfl_xor_sync(0xffffffffu, s0, 2);
        s1 += __shfl_xor_sync(0xffffffffu, s1, 2);
        s0 += __shfl_xor_sync(0xffffffffu, s0, 4);
        s1 += __shfl_xor_sync(0xffffffffu, s1, 4);
        float p0 = __expf(s0);
        float p1 = __expf(s1);
        den0 += p0; den1 += p1;
        ax = fmaf(p0, x0.x, ax); ay = fmaf(p0, x0.y, ay);
        az = fmaf(p0, x0.z, az); aw = fmaf(p0, x0.w, aw);
        ax = fmaf(p1, x1.x, ax); ay = fmaf(p1, x1.y, ay);
        az = fmaf(p1, x1.z, az); aw = fmaf(p1, x1.w, aw);
        x0 = x2; x1 = x3; x2 = nx0; x3 = nx1;
    }
    if (j < cnt) {
        float s0 = lrelu(x0.x + xr4.x) * a4.x
                 + lrelu(x0.y + xr4.y) * a4.y
                 + lrelu(x0.z + xr4.z) * a4.z
                 + lrelu(x0.w + xr4.w) * a4.w;
        s0 += __shfl_xor_sync(0xffffffffu, s0, 1);
        s0 += __shfl_xor_sync(0xffffffffu, s0, 2);
        s0 += __shfl_xor_sync(0xffffffffu, s0, 4);
        float p0 = __expf(s0);
        den0 += p0;
        ax = fmaf(p0, x0.x, ax); ay = fmaf(p0, x0.y, ay);
        az = fmaf(p0, x0.z, az); aw = fmaf(p0, x0.w, aw);
    }
    float inv = 1.f / (den0 + den1);
    const float4 b4 = __ldg(reinterpret_cast<const float4*>(&b1[f0]));
    float4 o;
    o.x = ax * inv + b4.x; o.x = (o.x > 0.f) ? o.x : (__expf(o.x) - 1.f);
    o.y = ay * inv + b4.y; o.y = (o.y > 0.f) ? o.y : (__expf(o.y) - 1.f);
    o.z = az * inv + b4.z; o.z = (o.z > 0.f) ? o.z : (__expf(o.z) - 1.f);
    o.w = aw * inv + b4.w; o.w = (o.w > 0.f) ? o.w : (__expf(o.w) - 1.f);
    *reinterpret_cast<float4*>(&g_h[(size_t)n * D1 + f0]) = o;
}

// ---------------- layer 2 GEMM: xl2 = h@w2_l, xr2 = h@w2_r (f32x2) -------
#define TN2 32
#define G2T 160
__global__ __launch_bounds__(G2T) void gemm2_kernel(const float* __restrict__ wl,
                                                    const float* __restrict__ wr,
                                                    int nbeg, int nend) {
    __shared__ float hs[TN2][D1];
    int n0 = nbeg + blockIdx.x * TN2;
    int t = threadIdx.x;
    for (int idx = t; idx < TN2 * D1; idx += G2T) {
        int row = idx >> 7, col = idx & 127;
        int n = n0 + row;
        hs[row][col] = (n < nend) ? g_h[(size_t)n * D1 + col] : 0.f;
    }
    __syncthreads();
    int col = t % CLS;
    int q   = t / CLS;
    ull acc[8];
    #pragma unroll
    for (int r = 0; r < 8; r++) acc[r] = 0ull;
    for (int k = 0; k < D1; k++) {
        ull w2 = pk2(__ldg(&wl[k * CLS + col]), __ldg(&wr[k * CLS + col]));
        #pragma unroll
        for (int r = 0; r < 8; r++) {
            float hv = hs[q * 8 + r][k];
            acc[r] = fma2(pk2(hv, hv), w2, acc[r]);
        }
    }
    #pragma unroll
    for (int r = 0; r < 8; r++) {
        int n = n0 + q * 8 + r;
        if (n < nend) {
            float2 lr = upk2(acc[r]);
            g_xl2[(size_t)n * CLS + col] = lr.x;
            g_xr2[(size_t)n * CLS + col] = lr.y;
        }
    }
}

// ---------------- fused node kernel, layer 2 + log_softmax ---------------
__global__ void node2_kernel(const float* __restrict__ a2,
                             const float* __restrict__ b2,
                             float* __restrict__ out) {
    int n = (blockIdx.x * blockDim.x + threadIdx.x) >> 5;
    int lane = threadIdx.x & 31;
    if (n >= NN) return;
    bool act = (lane * 2) < CLS;
    int f0 = lane * 2;
    float2 xr2v = make_float2(0.f, 0.f), a2v = make_float2(0.f, 0.f);
    if (act) {
        xr2v = *reinterpret_cast<const float2*>(&g_xr2[(size_t)n * CLS + f0]);
        a2v  = __ldg(reinterpret_cast<const float2*>(&a2[f0]));
    }
    int beg = g_rowptr[n];
    int cnt = g_rowptr[n + 1] - beg;
    const int* cs = g_csrc + beg;

    float den0 = 0.f, den1 = 0.f, ax = 0.f, ay = 0.f;

    int idx0 = cs[0];
    int idx1 = (1 < cnt) ? cs[1] : 0;
    int idx2 = (2 < cnt) ? cs[2] : 0;
    int idx3 = (3 < cnt) ? cs[3] : 0;
    float2 zero2 = make_float2(0.f, 0.f);
    float2 x0 = act ? *reinterpret_cast<const float2*>(&g_xl2[(size_t)idx0 * CLS + f0]) : zero2;
    float2 x1 = act ? *reinterpret_cast<const float2*>(&g_xl2[(size_t)idx1 * CLS + f0]) : zero2;
    float2 x2 = act ? *reinterpret_cast<const float2*>(&g_xl2[(size_t)idx2 * CLS + f0]) : zero2;
    float2 x3 = act ? *reinterpret_cast<const float2*>(&g_xl2[(size_t)idx3 * CLS + f0]) : zero2;

    int j = 0;
    for (; j + 1 < cnt; j += 2) {
        int i4 = (j + 4 < cnt) ? cs[j + 4] : 0;
        int i5 = (j + 5 < cnt) ? cs[j + 5] : 0;
        const float2 nx0 = act ? *reinterpret_cast<const float2*>(&g_xl2[(size_t)i4 * CLS + f0]) : zero2;
        const float2 nx1 = act ? *reinterpret_cast<const float2*>(&g_xl2[(size_t)i5 * CLS + f0]) : zero2;

        float s0 = lrelu(x0.x + xr2v.x) * a2v.x + lrelu(x0.y + xr2v.y) * a2v.y;
        float s1 = lrelu(x1.x + xr2v.x) * a2v.x + lrelu(x1.y + xr2v.y) * a2v.y;
        #pragma unroll
        for (int off = 16; off > 0; off >>= 1) {
            s0 += __shfl_xor_sync(0xffffffffu, s0, off);
            s1 += __shfl_xor_sync(0xffffffffu, s1, off);
        }
        float p0 = __expf(s0);
        float p1 = __expf(s1);
        den0 += p0; den1 += p1;
        ax = fmaf(p0, x0.x, ax); ay = fmaf(p0, x0.y, ay);
        ax = fmaf(p1, x1.x, ax); ay = fmaf(p1, x1.y, ay);
        x0 = x2; x1 = x3; x2 = nx0; x3 = nx1;
    }
    if (j < cnt) {
        float s0 = lrelu(x0.x + xr2v.x) * a2v.x + lrelu(x0.y + xr2v.y) * a2v.y;
        #pragma unroll
        for (int off = 16; off > 0; off >>= 1)
            s0 += __shfl_xor_sync(0xffffffffu, s0, off);
        float p0 = __expf(s0);
        den0 += p0;
        ax = fmaf(p0, x0.x, ax); ay = fmaf(p0, x0.y, ay);
    }
    float inv = 1.f / (den0 + den1);
    float v0 = -CUDART_INF_F, v1 = -CUDART_INF_F;
    if (act) {
        v0 = ax * inv + __ldg(&b2[f0]);
        v1 = ay * inv + __ldg(&b2[f0 + 1]);
    }
    float mx = fmaxf(v0, v1);
    #pragma unroll
    for (int off = 16; off > 0; off >>= 1)
        mx = fmaxf(mx, __shfl_xor_sync(0xffffffffu, mx, off));
    float se = act ? (__expf(v0 - mx) + __expf(v1 - mx)) : 0.f;
    #pragma unroll
    for (int off = 16; off > 0; off >>= 1)
        se += __shfl_xor_sync(0xffffffffu, se, off);
    float lse = mx + logf(se);
    if (act) {
        float2 o = make_float2(v0 - lse, v1 - lse);
        *reinterpret_cast<float2*>(&out[(size_t)n * CLS + f0]) = o;
    }
}

// ---------------- stream/event objects (created at process start) -------
static cudaStream_t s_side;
static cudaEvent_t  s_ev_fork;
static cudaEvent_t  s_ev_join;
static cudaEvent_t  s_ev_h;
static cudaEvent_t  s_ev_g2a;
namespace {
struct StreamInit {
    StreamInit() {
        cudaStreamCreateWithFlags(&s_side, cudaStreamNonBlocking);
        cudaEventCreateWithFlags(&s_ev_fork, cudaEventDisableTiming);
        cudaEventCreateWithFlags(&s_ev_join, cudaEventDisableTiming);
        cudaEventCreateWithFlags(&s_ev_h, cudaEventDisableTiming);
        cudaEventCreateWithFlags(&s_ev_g2a, cudaEventDisableTiming);
        cudaFuncSetAttribute(gemm1_mma_kernel,
                             cudaFuncAttributeMaxDynamicSharedMemorySize, G1_SMEM);
    }
};
static StreamInit s_stream_init;
}

// ---------------- launch ----------------
extern "C" void kernel_launch(void* const* d_in, const int* in_sizes, int n_in,
                              void* d_out, int out_size) {
    const float* x    = (const float*)d_in[0];
    const int*   eiw  = (const int*)d_in[1];
    const float* w1_l = (const float*)d_in[2];
    const float* w1_r = (const float*)d_in[3];
    const float* a1   = (const float*)d_in[4];
    const float* b1   = (const float*)d_in[5];
    const float* w2_l = (const float*)d_in[6];
    const float* w2_r = (const float*)d_in[7];
    const float* a2   = (const float*)d_in[8];
    const float* b2   = (const float*)d_in[9];
    float*       out  = (float*)d_out;

    // fork: CSR build on side stream, weight prep + gemm1 on main stream
    cudaEventRecord(s_ev_fork, 0);
    cudaStreamWaitEvent(s_side, s_ev_fork, 0);

    detect_zero_kernel<<<(NN + 255) / 256, 256, 0, s_side>>>(eiw);
    conv_hist_kernel<<<(ET + 255) / 256, 256, 0, s_side>>>(eiw);
    scan1_kernel<<<NBLK, SCANB, 0, s_side>>>();
    scan2_kernel<<<1, 64, 0, s_side>>>();
    scan3_kernel<<<(NN + 255) / 256, 256, 0, s_side>>>();
    scatter_kernel<<<(ET + 255) / 256, 256, 0, s_side>>>();
    cudaEventRecord(s_ev_join, s_side);

    wprep_kernel<<<64, 256>>>(w1_l, w1_r);
    gemm1_mma_kernel<<<(NN + 127) / 128, 512, G1_SMEM>>>(x);

    // join CSR
    cudaStreamWaitEvent(0, s_ev_join, 0);

    node1_kernel<<<(NHALF * 32) / 256, 256>>>(a1, b1, 0, NHALF);
    cudaEventRecord(s_ev_h, 0);
    cudaStreamWaitEvent(s_side, s_ev_h, 0);
    gemm2_kernel<<<NHALF / TN2, G2T, 0, s_side>>>(w2_l, w2_r, 0, NHALF);
    cudaEventRecord(s_ev_g2a, s_side);

    node1_kernel<<<((NN - NHALF) * 32 + 255) / 256, 256>>>(a1, b1, NHALF, NN);
    gemm2_kernel<<<(NN - NHALF + TN2 - 1) / TN2, G2T>>>(w2_l, w2_r, NHALF, NN);

    cudaStreamWaitEvent(0, s_ev_g2a, 0);
    node2_kernel<<<(NN * 32 + 255) / 256, 256>>>(a2, b2, out);
}